// round 7
// baseline (speedup 1.0000x reference)
#include <cuda_runtime.h>
#include <math_constants.h>
#include <cstdint>

#define DIM 1024
#define NQ  8192
#define NM  8192

// Scratch (allocation-free rule: __device__ globals)
__device__ float g_Q[(size_t)NQ * DIM];                 // 32 MB (tf32-rounded)
__device__ float g_K[(size_t)NM * DIM];                 // 32 MB (tf32-rounded)
__device__ float g_V[(size_t)NM * DIM];                 // 32 MB (tf32-rounded)
__device__ float g_S[(size_t)NQ * NM];                  // 256 MB (fp32 scores -> rounded P)
__device__ float g_Xr[(size_t)NQ * DIM];                // 32 MB rounded x
__device__ float g_Cr[(size_t)NM * DIM];                // 32 MB rounded context
__device__ float g_Wqr[(size_t)DIM * DIM];              // 4 MB rounded Wq
__device__ float g_Wkr[(size_t)DIM * DIM];              // 4 MB rounded Wk
__device__ float g_Wvr[(size_t)DIM * DIM];              // 4 MB rounded Wv

// ---------------------------------------------------------------------------
// Tile config
// ---------------------------------------------------------------------------
static constexpr int BM = 128, BN = 128, BK = 32;
static constexpr int A_STRIDE = BK + 4;      // 36 floats/row
static constexpr int BN_STRIDE = BN + 8;     // 136 floats/row
static constexpr int ASZ = BM * A_STRIDE;    // 4608 floats per A buffer
static constexpr int BSZ = ASZ;
static constexpr int SMEM_FLOATS = 2 * ASZ + 2 * BSZ;          // 18432
static constexpr int SMEM_BYTES  = SMEM_FLOATS * 4;            // 73728

// Round fp32 to tf32 (round-to-nearest-away) IN MEMORY: +half-ULP then mask
// low 13 mantissa bits. HW truncation inside mma is then a no-op.
__device__ __forceinline__ float round_tf32(float f) {
    uint32_t b = (__float_as_uint(f) + 0x1000u) & 0xFFFFE000u;
    return __uint_as_float(b);
}

__device__ __forceinline__ void cp_async16(uint32_t smem_addr, const void* gptr) {
    asm volatile("cp.async.cg.shared.global [%0], [%1], 16;"
                 :: "r"(smem_addr), "l"(gptr));
}
__device__ __forceinline__ void cp_commit() {
    asm volatile("cp.async.commit_group;");
}
__device__ __forceinline__ void cp_wait1() {
    asm volatile("cp.async.wait_group 1;");
}

__device__ __forceinline__ uint32_t smem_u32(const void* p) {
    uint32_t a;
    asm("{ .reg .u64 t; cvta.to.shared.u64 t, %1; cvt.u32.u64 %0, t; }"
        : "=r"(a) : "l"(p));
    return a;
}

__device__ __forceinline__ void mma_tf32(float* c, const uint32_t* a, const uint32_t* b) {
    asm volatile(
        "mma.sync.aligned.m16n8k8.row.col.f32.tf32.tf32.f32 "
        "{%0,%1,%2,%3}, {%4,%5,%6,%7}, {%8,%9}, {%0,%1,%2,%3};"
        : "+f"(c[0]), "+f"(c[1]), "+f"(c[2]), "+f"(c[3])
        : "r"(a[0]), "r"(a[1]), "r"(a[2]), "r"(a[3]), "r"(b[0]), "r"(b[1]));
}

// ---------------------------------------------------------------------------
// Pre-round a buffer to tf32 (grid-stride float4 copy)
// ---------------------------------------------------------------------------
__global__ void __launch_bounds__(256)
round_copy(const float4* __restrict__ in, float4* __restrict__ out, int n4)
{
    for (int i = blockIdx.x * 256 + threadIdx.x; i < n4; i += gridDim.x * 256) {
        float4 v = in[i];
        v.x = round_tf32(v.x); v.y = round_tf32(v.y);
        v.z = round_tf32(v.z); v.w = round_tf32(v.w);
        out[i] = v;
    }
}

// ---------------------------------------------------------------------------
// TF32 mma.sync GEMM: C[M,N] = alpha * A[M,K] @ op(B) (+ bias)
// All inputs must be PRE-ROUNDED to tf32. ROUND_OUT rounds C for downstream mma.
//   TRANS_B=true : B is [N,K] row-major (A @ B^T)
//   TRANS_B=false: B is [K,N] row-major
// 256 threads, warp tile 64x32 (warps 2m x 4n), m16n8k8 fragments.
// ---------------------------------------------------------------------------
template <bool TRANS_B, bool HAS_BIAS, bool ROUND_OUT>
__global__ void __launch_bounds__(256, 2)
mma_gemm(const float* __restrict__ A, const float* __restrict__ B,
         const float* __restrict__ bias, float* __restrict__ C,
         int M, int N, int K, float alpha)
{
    extern __shared__ __align__(16) float smem[];
    float* As = smem;                  // [2][BM][A_STRIDE]
    float* Bs = smem + 2 * ASZ;

    const int tid  = threadIdx.x;
    const int wid  = tid >> 5;
    const int lane = tid & 31;
    const int gid  = lane >> 2;
    const int tig  = lane & 3;
    const int row0 = blockIdx.y * BM;
    const int col0 = blockIdx.x * BN;
    const int m0   = (wid & 1) * 64;
    const int n0   = (wid >> 1) * 32;

    const uint32_t s_as = smem_u32(As);
    const uint32_t s_bs = smem_u32(Bs);

    float acc[4][4][4];
#pragma unroll
    for (int i = 0; i < 4; i++)
#pragma unroll
        for (int j = 0; j < 4; j++)
#pragma unroll
            for (int r = 0; r < 4; r++) acc[i][j][r] = 0.0f;

    const int T = K / BK;

    auto load_tile = [&](int t) {
        const int buf = t & 1;
        const int kt  = t * BK;
#pragma unroll
        for (int i = 0; i < 4; i++) {
            const int j  = tid * 4 + i;
            const int r  = j >> 3;
            const int ck = j & 7;
            cp_async16(s_as + (buf * ASZ + r * A_STRIDE + ck * 4) * 4,
                       &A[(size_t)(row0 + r) * K + kt + ck * 4]);
        }
        if (TRANS_B) {
#pragma unroll
            for (int i = 0; i < 4; i++) {
                const int j  = tid * 4 + i;
                const int r  = j >> 3;
                const int ck = j & 7;
                cp_async16(s_bs + (buf * BSZ + r * A_STRIDE + ck * 4) * 4,
                           &B[(size_t)(col0 + r) * K + kt + ck * 4]);
            }
        } else {
#pragma unroll
            for (int i = 0; i < 4; i++) {
                const int j  = tid * 4 + i;
                const int r  = j >> 5;
                const int ck = j & 31;
                cp_async16(s_bs + (buf * BSZ + r * BN_STRIDE + ck * 4) * 4,
                           &B[(size_t)(kt + r) * N + col0 + ck * 4]);
            }
        }
    };

    load_tile(0);
    cp_commit();

    for (int t = 0; t < T; ++t) {
        if (t + 1 < T) load_tile(t + 1);
        cp_commit();
        cp_wait1();
        __syncthreads();

        const uint32_t* At = reinterpret_cast<const uint32_t*>(As + (t & 1) * ASZ);
        const uint32_t* Bt = reinterpret_cast<const uint32_t*>(Bs + (t & 1) * BSZ);

#pragma unroll
        for (int ks = 0; ks < 4; ks++) {
            const int k = ks * 8;
            uint32_t af[4][4];
#pragma unroll
            for (int i = 0; i < 4; i++) {
                const int m = m0 + i * 16;
                af[i][0] = At[(m + gid)     * A_STRIDE + k + tig];
                af[i][1] = At[(m + gid + 8) * A_STRIDE + k + tig];
                af[i][2] = At[(m + gid)     * A_STRIDE + k + tig + 4];
                af[i][3] = At[(m + gid + 8) * A_STRIDE + k + tig + 4];
            }
            uint32_t bf[4][2];
#pragma unroll
            for (int j = 0; j < 4; j++) {
                const int n = n0 + j * 8;
                if (TRANS_B) {
                    bf[j][0] = Bt[(n + gid) * A_STRIDE + k + tig];
                    bf[j][1] = Bt[(n + gid) * A_STRIDE + k + tig + 4];
                } else {
                    bf[j][0] = Bt[(k + tig)     * BN_STRIDE + n + gid];
                    bf[j][1] = Bt[(k + tig + 4) * BN_STRIDE + n + gid];
                }
            }
#pragma unroll
            for (int i = 0; i < 4; i++)
#pragma unroll
                for (int j = 0; j < 4; j++)
                    mma_tf32(acc[i][j], af[i], bf[j]);
        }
        __syncthreads();
    }

    // ---- epilogue ----
#pragma unroll
    for (int i = 0; i < 4; i++) {
        const int r_lo = row0 + m0 + i * 16 + gid;
        const int r_hi = r_lo + 8;
#pragma unroll
        for (int j = 0; j < 4; j++) {
            const int c = col0 + n0 + j * 8 + tig * 2;
            float2 lo, hi;
            lo.x = acc[i][j][0] * alpha;
            lo.y = acc[i][j][1] * alpha;
            hi.x = acc[i][j][2] * alpha;
            hi.y = acc[i][j][3] * alpha;
            if (HAS_BIAS) {
                const float2 bb = *reinterpret_cast<const float2*>(&bias[c]);
                lo.x += bb.x; lo.y += bb.y;
                hi.x += bb.x; hi.y += bb.y;
            }
            if (ROUND_OUT) {
                lo.x = round_tf32(lo.x); lo.y = round_tf32(lo.y);
                hi.x = round_tf32(hi.x); hi.y = round_tf32(hi.y);
            }
            *reinterpret_cast<float2*>(&C[(size_t)r_lo * N + c]) = lo;
            *reinterpret_cast<float2*>(&C[(size_t)r_hi * N + c]) = hi;
        }
    }
}

// ---------------------------------------------------------------------------
// In-place row softmax; output P rounded to tf32 (it feeds the PV mma).
// ---------------------------------------------------------------------------
__global__ void __launch_bounds__(256)
softmax_rows(float* __restrict__ S, int M)
{
    const int tid  = threadIdx.x;
    const int lane = tid & 31;
    const int warp = tid >> 5;
    float* row = S + (size_t)blockIdx.x * M;

    float4 v[8];
#pragma unroll
    for (int j = 0; j < 8; j++)
        v[j] = *reinterpret_cast<const float4*>(&row[(tid + j * 256) * 4]);

    float mx = -CUDART_INF_F;
#pragma unroll
    for (int j = 0; j < 8; j++)
        mx = fmaxf(mx, fmaxf(fmaxf(v[j].x, v[j].y), fmaxf(v[j].z, v[j].w)));
#pragma unroll
    for (int o = 16; o > 0; o >>= 1)
        mx = fmaxf(mx, __shfl_xor_sync(0xffffffffu, mx, o));

    __shared__ float red_max[8];
    __shared__ float red_sum[8];
    if (lane == 0) red_max[warp] = mx;
    __syncthreads();
    if (tid < 32) {
        float t = (tid < 8) ? red_max[tid] : -CUDART_INF_F;
#pragma unroll
        for (int o = 4; o > 0; o >>= 1)
            t = fmaxf(t, __shfl_xor_sync(0xffffffffu, t, o));
        if (tid == 0) red_max[0] = t;
    }
    __syncthreads();
    mx = red_max[0];

    float s = 0.0f;
#pragma unroll
    for (int j = 0; j < 8; j++) {
        v[j].x = expf(v[j].x - mx);
        v[j].y = expf(v[j].y - mx);
        v[j].z = expf(v[j].z - mx);
        v[j].w = expf(v[j].w - mx);
        s += v[j].x + v[j].y + v[j].z + v[j].w;
    }
#pragma unroll
    for (int o = 16; o > 0; o >>= 1)
        s += __shfl_xor_sync(0xffffffffu, s, o);
    if (lane == 0) red_sum[warp] = s;
    __syncthreads();
    if (tid < 32) {
        float t = (tid < 8) ? red_sum[tid] : 0.0f;
#pragma unroll
        for (int o = 4; o > 0; o >>= 1)
            t += __shfl_xor_sync(0xffffffffu, t, o);
        if (tid == 0) red_sum[0] = t;
    }
    __syncthreads();
    const float inv = 1.0f / red_sum[0];

#pragma unroll
    for (int j = 0; j < 8; j++) {
        v[j].x = round_tf32(v[j].x * inv);
        v[j].y = round_tf32(v[j].y * inv);
        v[j].z = round_tf32(v[j].z * inv);
        v[j].w = round_tf32(v[j].w * inv);
        *reinterpret_cast<float4*>(&row[(tid + j * 256) * 4]) = v[j];
    }
}

// ---------------------------------------------------------------------------
extern "C" void kernel_launch(void* const* d_in, const int* in_sizes, int n_in,
                              void* d_out, int out_size)
{
    const float* x   = (const float*)d_in[0];
    const float* ctx = (const float*)d_in[1];
    const float* Wq  = (const float*)d_in[2];
    const float* bq  = (const float*)d_in[3];
    const float* Wk  = (const float*)d_in[4];
    const float* bk  = (const float*)d_in[5];
    const float* Wv  = (const float*)d_in[6];
    const float* bv  = (const float*)d_in[7];
    float* out = (float*)d_out;

    float *Q, *K, *V, *S, *Xr, *Cr, *Wqr, *Wkr, *Wvr;
    cudaGetSymbolAddress((void**)&Q, g_Q);
    cudaGetSymbolAddress((void**)&K, g_K);
    cudaGetSymbolAddress((void**)&V, g_V);
    cudaGetSymbolAddress((void**)&S, g_S);
    cudaGetSymbolAddress((void**)&Xr, g_Xr);
    cudaGetSymbolAddress((void**)&Cr, g_Cr);
    cudaGetSymbolAddress((void**)&Wqr, g_Wqr);
    cudaGetSymbolAddress((void**)&Wkr, g_Wkr);
    cudaGetSymbolAddress((void**)&Wvr, g_Wvr);

    cudaFuncSetAttribute(mma_gemm<false, true,  true>,
                         cudaFuncAttributeMaxDynamicSharedMemorySize, SMEM_BYTES);
    cudaFuncSetAttribute(mma_gemm<true,  false, false>,
                         cudaFuncAttributeMaxDynamicSharedMemorySize, SMEM_BYTES);
    cudaFuncSetAttribute(mma_gemm<false, false, false>,
                         cudaFuncAttributeMaxDynamicSharedMemorySize, SMEM_BYTES);

    const dim3 blk(256);
    const float scale = 0.03125f;   // 1/sqrt(1024)
    const int nW4 = DIM * DIM / 4;
    const int nX4 = NQ * DIM / 4;

    // Pre-round raw inputs to tf32
    round_copy<<<592, 256>>>((const float4*)x,   (float4*)Xr,  nX4);
    round_copy<<<592, 256>>>((const float4*)ctx, (float4*)Cr,  nX4);
    round_copy<<<296, 256>>>((const float4*)Wq,  (float4*)Wqr, nW4);
    round_copy<<<296, 256>>>((const float4*)Wk,  (float4*)Wkr, nW4);
    round_copy<<<296, 256>>>((const float4*)Wv,  (float4*)Wvr, nW4);

    // Projections (outputs rounded to tf32 for the attention GEMMs)
    mma_gemm<false, true, true><<<dim3(DIM / 128, NQ / 128), blk, SMEM_BYTES>>>(
        Xr, Wqr, bq, Q, NQ, DIM, DIM, 1.0f);
    mma_gemm<false, true, true><<<dim3(DIM / 128, NM / 128), blk, SMEM_BYTES>>>(
        Cr, Wkr, bk, K, NM, DIM, DIM, 1.0f);
    mma_gemm<false, true, true><<<dim3(DIM / 128, NM / 128), blk, SMEM_BYTES>>>(
        Cr, Wvr, bv, V, NM, DIM, DIM, 1.0f);

    // Scores: S = scale * Q @ K^T  (full fp32 out; softmax consumes it)
    mma_gemm<true, false, false><<<dim3(NM / 128, NQ / 128), blk, SMEM_BYTES>>>(
        Q, K, nullptr, S, NQ, NM, DIM, scale);

    // Softmax (rounds P to tf32)
    softmax_rows<<<NQ, 256>>>(S, NM);

    // Output: out = P @ V (full fp32 out)
    mma_gemm<false, false, false><<<dim3(DIM / 128, NQ / 128), blk, SMEM_BYTES>>>(
        S, V, nullptr, out, NQ, DIM, NM, 1.0f);
}

// round 9
// speedup vs baseline: 1.0220x; 1.0220x over previous
#include <cuda_runtime.h>
#include <math_constants.h>
#include <cstdint>

#define DIM 1024
#define NQ  8192
#define NM  8192

// Scratch (allocation-free rule: __device__ globals)
__device__ float g_Q[(size_t)NQ * DIM];                 // tf32-rounded
__device__ float g_K[(size_t)NM * DIM];                 // tf32-rounded
__device__ float g_V[(size_t)NM * DIM];                 // tf32-rounded
__device__ float g_S[(size_t)NQ * NM];                  // fp32 scores -> rounded P
__device__ float g_Xr[(size_t)NQ * DIM];                // rounded x
__device__ float g_Cr[(size_t)NM * DIM];                // rounded context
__device__ float g_Wqr[(size_t)DIM * DIM];              // rounded Wq
__device__ float g_Wkr[(size_t)DIM * DIM];              // rounded Wk
__device__ float g_Wvr[(size_t)DIM * DIM];              // rounded Wv

// ---------------------------------------------------------------------------
// Tile config
// ---------------------------------------------------------------------------
static constexpr int BM = 128, BN = 128, BK = 32;
static constexpr int A_STRIDE = BK + 4;      // 36 floats/row (rows stagger 4 banks)
static constexpr int BN_STRIDE = BN + 8;     // 136 floats/row
static constexpr int ASZ = BM * A_STRIDE;    // 4608 floats per buffer
static constexpr int BSZ = ASZ;
static constexpr int SMEM_FLOATS = 2 * ASZ + 2 * BSZ;          // 18432
static constexpr int SMEM_BYTES  = SMEM_FLOATS * 4;            // 73728

// Round fp32 to tf32 (round-to-nearest-away) in memory.
__device__ __forceinline__ float round_tf32(float f) {
    uint32_t b = (__float_as_uint(f) + 0x1000u) & 0xFFFFE000u;
    return __uint_as_float(b);
}

__device__ __forceinline__ void cp_async16(uint32_t smem_addr, const void* gptr) {
    asm volatile("cp.async.cg.shared.global [%0], [%1], 16;"
                 :: "r"(smem_addr), "l"(gptr));
}
__device__ __forceinline__ void cp_commit() {
    asm volatile("cp.async.commit_group;");
}
__device__ __forceinline__ void cp_wait1() {
    asm volatile("cp.async.wait_group 1;");
}

__device__ __forceinline__ uint32_t smem_u32(const void* p) {
    uint32_t a;
    asm("{ .reg .u64 t; cvta.to.shared.u64 t, %1; cvt.u32.u64 %0, t; }"
        : "=r"(a) : "l"(p));
    return a;
}

// tf32 fragment loads via b16 ldmatrix: one m8n8.b16 tile == 8x4 tf32 block,
// thread l receives 32-bit element (l/4, l%4) — exactly the mma mapping.
__device__ __forceinline__ void ldsm_x4(uint32_t* r, uint32_t addr) {
    asm volatile("ldmatrix.sync.aligned.m8n8.x4.shared.b16 {%0,%1,%2,%3}, [%4];"
                 : "=r"(r[0]), "=r"(r[1]), "=r"(r[2]), "=r"(r[3]) : "r"(addr));
}
__device__ __forceinline__ void ldsm_x2(uint32_t* r, uint32_t addr) {
    asm volatile("ldmatrix.sync.aligned.m8n8.x2.shared.b16 {%0,%1}, [%2];"
                 : "=r"(r[0]), "=r"(r[1]) : "r"(addr));
}

__device__ __forceinline__ void mma_tf32(float* c, const uint32_t* a, const uint32_t* b) {
    asm volatile(
        "mma.sync.aligned.m16n8k8.row.col.f32.tf32.tf32.f32 "
        "{%0,%1,%2,%3}, {%4,%5,%6,%7}, {%8,%9}, {%0,%1,%2,%3};"
        : "+f"(c[0]), "+f"(c[1]), "+f"(c[2]), "+f"(c[3])
        : "r"(a[0]), "r"(a[1]), "r"(a[2]), "r"(a[3]), "r"(b[0]), "r"(b[1]));
}

// ---------------------------------------------------------------------------
// Pre-round a buffer to tf32 (grid-stride float4 copy)
// ---------------------------------------------------------------------------
__global__ void __launch_bounds__(256)
round_copy(const float4* __restrict__ in, float4* __restrict__ out, int n4)
{
    for (int i = blockIdx.x * 256 + threadIdx.x; i < n4; i += gridDim.x * 256) {
        float4 v = in[i];
        v.x = round_tf32(v.x); v.y = round_tf32(v.y);
        v.z = round_tf32(v.z); v.w = round_tf32(v.w);
        out[i] = v;
    }
}

// ---------------------------------------------------------------------------
// TF32 mma.sync GEMM, ldmatrix fragment loads. Inputs pre-rounded to tf32.
//   TRANS_B=true : B is [N,K] row-major -> Bs [n][k], B frags via ldmatrix.x2
//   TRANS_B=false: B is [K,N] row-major -> Bs [k][n], B frags scalar LDS
// 256 threads, warp tile 64x32 (warps 2m x 4n), m16n8k8 fragments.
// ---------------------------------------------------------------------------
template <bool TRANS_B, bool HAS_BIAS, bool ROUND_OUT>
__global__ void __launch_bounds__(256, 2)
mma_gemm(const float* __restrict__ A, const float* __restrict__ B,
         const float* __restrict__ bias, float* __restrict__ C,
         int M, int N, int K, float alpha)
{
    extern __shared__ __align__(16) float smem[];
    float* As = smem;                  // [2][BM][A_STRIDE]
    float* Bs = smem + 2 * ASZ;

    const int tid  = threadIdx.x;
    const int wid  = tid >> 5;
    const int lane = tid & 31;
    const int gid  = lane >> 2;
    const int tig  = lane & 3;
    const int row0 = blockIdx.y * BM;
    const int col0 = blockIdx.x * BN;
    const int m0   = (wid & 1) * 64;
    const int n0   = (wid >> 1) * 32;

    const uint32_t s_as = smem_u32(As);
    const uint32_t s_bs = smem_u32(Bs);

    // Per-thread ldmatrix base offsets (in bytes, within one buffer).
    // A x4: matrix i = lane/8 covers rows m0+(i&1)*8 .. +7 at k-col (i>>1)*4.
    const int li = lane >> 3;          // 0..3
    const int lr = lane & 7;
    const uint32_t a_lm_off =
        (uint32_t)(((m0 + (li & 1) * 8 + lr) * A_STRIDE + (li >> 1) * 4) * 4);
    // B x2 (TRANS_B): matrix i = (lane>>3)&1 covers rows n0+lr at k-col i*4.
    const uint32_t b_lm_off =
        (uint32_t)(((n0 + lr) * A_STRIDE + ((lane >> 3) & 1) * 4) * 4);

    float acc[4][4][4];
#pragma unroll
    for (int i = 0; i < 4; i++)
#pragma unroll
        for (int j = 0; j < 4; j++)
#pragma unroll
            for (int r = 0; r < 4; r++) acc[i][j][r] = 0.0f;

    const int T = K / BK;

    auto load_tile = [&](int t) {
        const int buf = t & 1;
        const int kt  = t * BK;
#pragma unroll
        for (int i = 0; i < 4; i++) {
            const int j  = tid * 4 + i;
            const int r  = j >> 3;
            const int ck = j & 7;
            cp_async16(s_as + (buf * ASZ + r * A_STRIDE + ck * 4) * 4,
                       &A[(size_t)(row0 + r) * K + kt + ck * 4]);
        }
        if (TRANS_B) {
#pragma unroll
            for (int i = 0; i < 4; i++) {
                const int j  = tid * 4 + i;
                const int r  = j >> 3;
                const int ck = j & 7;
                cp_async16(s_bs + (buf * BSZ + r * A_STRIDE + ck * 4) * 4,
                           &B[(size_t)(col0 + r) * K + kt + ck * 4]);
            }
        } else {
#pragma unroll
            for (int i = 0; i < 4; i++) {
                const int j  = tid * 4 + i;
                const int r  = j >> 5;
                const int ck = j & 31;
                cp_async16(s_bs + (buf * BSZ + r * BN_STRIDE + ck * 4) * 4,
                           &B[(size_t)(kt + r) * N + col0 + ck * 4]);
            }
        }
    };

    load_tile(0);
    cp_commit();

    for (int t = 0; t < T; ++t) {
        if (t + 1 < T) load_tile(t + 1);
        cp_commit();
        cp_wait1();
        __syncthreads();

        const uint32_t buf = (uint32_t)(t & 1);
        const uint32_t sA = s_as + buf * (ASZ * 4);
        const uint32_t sB = s_bs + buf * (BSZ * 4);
        const uint32_t* Bt = reinterpret_cast<const uint32_t*>(Bs + buf * BSZ);

#pragma unroll
        for (int ks = 0; ks < 4; ks++) {
            const int k = ks * 8;
            uint32_t af[4][4];
#pragma unroll
            for (int i = 0; i < 4; i++) {
                // fragment (m0 + i*16, k): base + i*16 rows + ks*8 cols
                ldsm_x4(af[i], sA + a_lm_off +
                        (uint32_t)((i * 16 * A_STRIDE + k) * 4));
            }
            uint32_t bf[4][2];
#pragma unroll
            for (int j = 0; j < 4; j++) {
                if (TRANS_B) {
                    ldsm_x2(bf[j], sB + b_lm_off +
                            (uint32_t)((j * 8 * A_STRIDE + k) * 4));
                } else {
                    const int n = n0 + j * 8;
                    bf[j][0] = Bt[(k + tig)     * BN_STRIDE + n + gid];
                    bf[j][1] = Bt[(k + tig + 4) * BN_STRIDE + n + gid];
                }
            }
#pragma unroll
            for (int i = 0; i < 4; i++)
#pragma unroll
                for (int j = 0; j < 4; j++)
                    mma_tf32(acc[i][j], af[i], bf[j]);
        }
        __syncthreads();
    }

    // ---- epilogue ----
#pragma unroll
    for (int i = 0; i < 4; i++) {
        const int r_lo = row0 + m0 + i * 16 + gid;
        const int r_hi = r_lo + 8;
#pragma unroll
        for (int j = 0; j < 4; j++) {
            const int c = col0 + n0 + j * 8 + tig * 2;
            float2 lo, hi;
            lo.x = acc[i][j][0] * alpha;
            lo.y = acc[i][j][1] * alpha;
            hi.x = acc[i][j][2] * alpha;
            hi.y = acc[i][j][3] * alpha;
            if (HAS_BIAS) {
                const float2 bb = *reinterpret_cast<const float2*>(&bias[c]);
                lo.x += bb.x; lo.y += bb.y;
                hi.x += bb.x; hi.y += bb.y;
            }
            if (ROUND_OUT) {
                lo.x = round_tf32(lo.x); lo.y = round_tf32(lo.y);
                hi.x = round_tf32(hi.x); hi.y = round_tf32(hi.y);
            }
            *reinterpret_cast<float2*>(&C[(size_t)r_lo * N + c]) = lo;
            *reinterpret_cast<float2*>(&C[(size_t)r_hi * N + c]) = hi;
        }
    }
}

// ---------------------------------------------------------------------------
// In-place row softmax; output P rounded to tf32 (feeds the PV mma).
// ---------------------------------------------------------------------------
__global__ void __launch_bounds__(256)
softmax_rows(float* __restrict__ S, int M)
{
    const int tid  = threadIdx.x;
    const int lane = tid & 31;
    const int warp = tid >> 5;
    float* row = S + (size_t)blockIdx.x * M;

    float4 v[8];
#pragma unroll
    for (int j = 0; j < 8; j++)
        v[j] = *reinterpret_cast<const float4*>(&row[(tid + j * 256) * 4]);

    float mx = -CUDART_INF_F;
#pragma unroll
    for (int j = 0; j < 8; j++)
        mx = fmaxf(mx, fmaxf(fmaxf(v[j].x, v[j].y), fmaxf(v[j].z, v[j].w)));
#pragma unroll
    for (int o = 16; o > 0; o >>= 1)
        mx = fmaxf(mx, __shfl_xor_sync(0xffffffffu, mx, o));

    __shared__ float red_max[8];
    __shared__ float red_sum[8];
    if (lane == 0) red_max[warp] = mx;
    __syncthreads();
    if (tid < 32) {
        float t = (tid < 8) ? red_max[tid] : -CUDART_INF_F;
#pragma unroll
        for (int o = 4; o > 0; o >>= 1)
            t = fmaxf(t, __shfl_xor_sync(0xffffffffu, t, o));
        if (tid == 0) red_max[0] = t;
    }
    __syncthreads();
    mx = red_max[0];

    float s = 0.0f;
#pragma unroll
    for (int j = 0; j < 8; j++) {
        v[j].x = expf(v[j].x - mx);
        v[j].y = expf(v[j].y - mx);
        v[j].z = expf(v[j].z - mx);
        v[j].w = expf(v[j].w - mx);
        s += v[j].x + v[j].y + v[j].z + v[j].w;
    }
#pragma unroll
    for (int o = 16; o > 0; o >>= 1)
        s += __shfl_xor_sync(0xffffffffu, s, o);
    if (lane == 0) red_sum[warp] = s;
    __syncthreads();
    if (tid < 32) {
        float t = (tid < 8) ? red_sum[tid] : 0.0f;
#pragma unroll
        for (int o = 4; o > 0; o >>= 1)
            t += __shfl_xor_sync(0xffffffffu, t, o);
        if (tid == 0) red_sum[0] = t;
    }
    __syncthreads();
    const float inv = 1.0f / red_sum[0];

#pragma unroll
    for (int j = 0; j < 8; j++) {
        v[j].x = round_tf32(v[j].x * inv);
        v[j].y = round_tf32(v[j].y * inv);
        v[j].z = round_tf32(v[j].z * inv);
        v[j].w = round_tf32(v[j].w * inv);
        *reinterpret_cast<float4*>(&row[(tid + j * 256) * 4]) = v[j];
    }
}

// ---------------------------------------------------------------------------
extern "C" void kernel_launch(void* const* d_in, const int* in_sizes, int n_in,
                              void* d_out, int out_size)
{
    const float* x   = (const float*)d_in[0];
    const float* ctx = (const float*)d_in[1];
    const float* Wq  = (const float*)d_in[2];
    const float* bq  = (const float*)d_in[3];
    const float* Wk  = (const float*)d_in[4];
    const float* bk  = (const float*)d_in[5];
    const float* Wv  = (const float*)d_in[6];
    const float* bv  = (const float*)d_in[7];
    float* out = (float*)d_out;

    float *Q, *K, *V, *S, *Xr, *Cr, *Wqr, *Wkr, *Wvr;
    cudaGetSymbolAddress((void**)&Q, g_Q);
    cudaGetSymbolAddress((void**)&K, g_K);
    cudaGetSymbolAddress((void**)&V, g_V);
    cudaGetSymbolAddress((void**)&S, g_S);
    cudaGetSymbolAddress((void**)&Xr, g_Xr);
    cudaGetSymbolAddress((void**)&Cr, g_Cr);
    cudaGetSymbolAddress((void**)&Wqr, g_Wqr);
    cudaGetSymbolAddress((void**)&Wkr, g_Wkr);
    cudaGetSymbolAddress((void**)&Wvr, g_Wvr);

    cudaFuncSetAttribute(mma_gemm<false, true,  true>,
                         cudaFuncAttributeMaxDynamicSharedMemorySize, SMEM_BYTES);
    cudaFuncSetAttribute(mma_gemm<true,  false, false>,
                         cudaFuncAttributeMaxDynamicSharedMemorySize, SMEM_BYTES);
    cudaFuncSetAttribute(mma_gemm<false, false, false>,
                         cudaFuncAttributeMaxDynamicSharedMemorySize, SMEM_BYTES);

    const dim3 blk(256);
    const float scale = 0.03125f;   // 1/sqrt(1024)
    const int nW4 = DIM * DIM / 4;
    const int nX4 = NQ * DIM / 4;

    // Pre-round raw inputs to tf32
    round_copy<<<592, 256>>>((const float4*)x,   (float4*)Xr,  nX4);
    round_copy<<<592, 256>>>((const float4*)ctx, (float4*)Cr,  nX4);
    round_copy<<<296, 256>>>((const float4*)Wq,  (float4*)Wqr, nW4);
    round_copy<<<296, 256>>>((const float4*)Wk,  (float4*)Wkr, nW4);
    round_copy<<<296, 256>>>((const float4*)Wv,  (float4*)Wvr, nW4);

    // Projections (outputs rounded to tf32 for the attention GEMMs)
    mma_gemm<false, true, true><<<dim3(DIM / 128, NQ / 128), blk, SMEM_BYTES>>>(
        Xr, Wqr, bq, Q, NQ, DIM, DIM, 1.0f);
    mma_gemm<false, true, true><<<dim3(DIM / 128, NM / 128), blk, SMEM_BYTES>>>(
        Cr, Wkr, bk, K, NM, DIM, DIM, 1.0f);
    mma_gemm<false, true, true><<<dim3(DIM / 128, NM / 128), blk, SMEM_BYTES>>>(
        Cr, Wvr, bv, V, NM, DIM, DIM, 1.0f);

    // Scores: S = scale * Q @ K^T  (full fp32 out; softmax consumes it)
    mma_gemm<true, false, false><<<dim3(NM / 128, NQ / 128), blk, SMEM_BYTES>>>(
        Q, K, nullptr, S, NQ, NM, DIM, scale);

    // Softmax (rounds P to tf32)
    softmax_rows<<<NQ, 256>>>(S, NM);

    // Output: out = P @ V (full fp32 out)
    mma_gemm<false, false, false><<<dim3(DIM / 128, NQ / 128), blk, SMEM_BYTES>>>(
        S, V, nullptr, out, NQ, DIM, NM, 1.0f);
}